// round 15
// baseline (speedup 1.0000x reference)
#include <cuda_runtime.h>
#include <cuda_fp16.h>
#include <cstdint>

#define BB 64
#define TT 256
#define II 1024
#define HH 2048
#define OO 1024

// ---------------- device scratch ----------------
__device__ __half g_xh[(size_t)BB * TT * II];
__device__ __half g_Wax[(size_t)HH * II];
__device__ __half g_Waa[(size_t)HH * HH];
__device__ __half g_Wya[(size_t)OO * HH];
__device__ float  g_Z[(size_t)TT * BB * HH];                 // x W_ax^T + b_ax + b_aa
__device__ __half g_ahist[(size_t)(TT + 1) * BB * HH];       // all hidden states
__device__ unsigned g_barh[512];                              // [(mh*8+g)*32]: group counters

// ---------------- helpers ----------------
__device__ __forceinline__ uint32_t sptr(const void* p) {
    return (uint32_t)__cvta_generic_to_shared(p);
}
__device__ __forceinline__ void cp_async16(const void* dst_smem, const void* src) {
    asm volatile("cp.async.cg.shared.global [%0], [%1], 16;"
                 :: "r"(sptr(dst_smem)), "l"(src));
}
__device__ __forceinline__ void cp_commit() { asm volatile("cp.async.commit_group;"); }
__device__ __forceinline__ void cp_wait0()  { asm volatile("cp.async.wait_group 0;"); }
__device__ __forceinline__ void cp_wait1()  { asm volatile("cp.async.wait_group 1;"); }

__device__ __forceinline__ void ldsm4(uint32_t& r0, uint32_t& r1, uint32_t& r2, uint32_t& r3,
                                      const void* p) {
    asm volatile("ldmatrix.sync.aligned.m8n8.x4.shared.b16 {%0,%1,%2,%3},[%4];"
                 : "=r"(r0), "=r"(r1), "=r"(r2), "=r"(r3) : "r"(sptr(p)));
}
__device__ __forceinline__ void mma16816(float* c, const uint32_t* a,
                                         uint32_t b0, uint32_t b1) {
    asm volatile("mma.sync.aligned.m16n8k16.row.col.f32.f16.f16.f32 "
                 "{%0,%1,%2,%3},{%4,%5,%6,%7},{%8,%9},{%0,%1,%2,%3};"
                 : "+f"(c[0]), "+f"(c[1]), "+f"(c[2]), "+f"(c[3])
                 : "r"(a[0]), "r"(a[1]), "r"(a[2]), "r"(a[3]), "r"(b0), "r"(b1));
}
__device__ __forceinline__ float sigf(float v) { return 1.0f / (1.0f + __expf(-v)); }

__device__ __forceinline__ unsigned ld_acq(const unsigned* p) {
    unsigned v;
    asm volatile("ld.acquire.gpu.u32 %0, [%1];" : "=r"(v) : "l"(p));
    return v;
}
__device__ __forceinline__ void red_rel_add1(unsigned* p) {
    asm volatile("red.release.gpu.add.u32 [%0], 1;" :: "l"(p));
}

// ---------------- prep (vectorized x4) ----------------
#define NX  ((size_t)BB * TT * II)
#define NAA ((size_t)HH * HH)
#define NAX ((size_t)HH * II)
#define NYA ((size_t)OO * HH)
#define NA0 ((size_t)BB * HH)
#define NPREP4 ((NX + NAA + NAX + NYA + NA0) / 4)

__device__ __forceinline__ void cvt4(__half* dst, const float* src, size_t i4) {
    float4 v = *(const float4*)(src + i4 * 4);
    __half2 h0 = __floats2half2_rn(v.x, v.y);
    __half2 h1 = __floats2half2_rn(v.z, v.w);
    *(uint2*)(dst + i4 * 4) = make_uint2(*(uint32_t*)&h0, *(uint32_t*)&h1);
}

__global__ void prep_kernel(const float* __restrict__ x, const float* __restrict__ Waa,
                            const float* __restrict__ Wax, const float* __restrict__ Wya) {
    size_t i = (size_t)blockIdx.x * blockDim.x + threadIdx.x;
    if (i < 512) g_barh[i] = 0u;
    if (i < NX / 4) { cvt4(g_xh, x, i); return; }
    i -= NX / 4;
    if (i < NAA / 4) { cvt4(g_Waa, Waa, i); return; }
    i -= NAA / 4;
    if (i < NAX / 4) { cvt4(g_Wax, Wax, i); return; }
    i -= NAX / 4;
    if (i < NYA / 4) { cvt4(g_Wya, Wya, i); return; }
    i -= NYA / 4;
    if (i < NA0 / 4) { *(uint2*)(g_ahist + i * 4) = make_uint2(0u, 0u); }  // a_0 = 0
}

// ---------------- big parallel GEMM (xproj MODE 0 / ypass MODE 1) ----------------
#define XP_SMEM (2 * (2 * 128 * 72 * 2))

template <int MODE>
__global__ void __launch_bounds__(256) big_gemm(const float* __restrict__ c0,
                                                const float* __restrict__ c1,
                                                float* __restrict__ outp) {
    constexpr int KD = (MODE == 0) ? II : HH;
    constexpr int NCHX = KD / 64;
    extern __shared__ __align__(16) unsigned char smraw[];
    __half* As = (__half*)smraw;                       // [2][128][72]
    __half* Bs = (__half*)(smraw + 2 * 128 * 72 * 2);  // [2][128][72]

    const int tid = threadIdx.x;
    const int lane = tid & 31, warp = tid >> 5;
    const int n0 = blockIdx.x * 128;
    const int m0 = blockIdx.y * 128;
    const int wm = (warp >> 1) * 32;
    const int wn = (warp & 1) * 64;
    const int gr = lane >> 2, q = lane & 3;

    const int arow = ((lane >> 3) & 1) * 8 + (lane & 7);
    const int akoff = (lane >> 4) * 8;
    const int brow = (lane >> 4) * 8 + (lane & 7);
    const int bkoff = ((lane >> 3) & 1) * 8;

    const __half* Wg = (MODE == 0) ? g_Wax : g_Wya;

    float acc[2][8][4];
#pragma unroll
    for (int f = 0; f < 2; ++f)
#pragma unroll
        for (int bt = 0; bt < 8; ++bt)
#pragma unroll
            for (int c = 0; c < 4; ++c) acc[f][bt][c] = 0.0f;

    auto load_chunk = [&](int buf, int ck) {
#pragma unroll
        for (int r = 0; r < 4; ++r) {
            int u = tid + r * 256;
            int row = u >> 3, cg = u & 7;
            int m = m0 + row;
            const __half* asrc;
            if (MODE == 0) {
                int t = m >> 6, b = m & 63;
                asrc = g_xh + ((size_t)b * TT + t) * II + ck * 64 + cg * 8;
            } else {
                asrc = g_ahist + (size_t)(m + 64) * HH + ck * 64 + cg * 8;
            }
            cp_async16(As + buf * (128 * 72) + row * 72 + cg * 8, asrc);
            cp_async16(Bs + buf * (128 * 72) + row * 72 + cg * 8,
                       Wg + (size_t)(n0 + row) * KD + ck * 64 + cg * 8);
        }
    };

    load_chunk(0, 0);
    cp_commit();
    for (int ck = 0; ck < NCHX; ++ck) {
        if (ck + 1 < NCHX) { load_chunk((ck + 1) & 1, ck + 1); cp_commit(); cp_wait1(); }
        else cp_wait0();
        __syncthreads();
        const __half* Ab = As + (ck & 1) * (128 * 72);
        const __half* Bb = Bs + (ck & 1) * (128 * 72);
#pragma unroll
        for (int s = 0; s < 4; ++s) {
            uint32_t a[2][4];
#pragma unroll
            for (int f = 0; f < 2; ++f)
                ldsm4(a[f][0], a[f][1], a[f][2], a[f][3],
                      Ab + (wm + f * 16 + arow) * 72 + s * 16 + akoff);
#pragma unroll
            for (int bp = 0; bp < 4; ++bp) {
                uint32_t b0, b1, b2, b3;
                ldsm4(b0, b1, b2, b3,
                      Bb + (wn + bp * 16 + brow) * 72 + s * 16 + bkoff);
#pragma unroll
                for (int f = 0; f < 2; ++f) {
                    mma16816(acc[f][2 * bp],     a[f], b0, b1);
                    mma16816(acc[f][2 * bp + 1], a[f], b2, b3);
                }
            }
        }
        __syncthreads();
    }

    float bs0[8], bs1[8];
#pragma unroll
    for (int bt = 0; bt < 8; ++bt) {
        int n = n0 + wn + bt * 8 + 2 * q;
        if (MODE == 0) { bs0[bt] = c0[n] + c1[n]; bs1[bt] = c0[n + 1] + c1[n + 1]; }
        else           { bs0[bt] = c0[n];         bs1[bt] = c0[n + 1]; }
    }
#pragma unroll
    for (int f = 0; f < 2; ++f) {
#pragma unroll
        for (int bt = 0; bt < 8; ++bt) {
            int mlo = wm + f * 16 + gr;
            int n = wn + bt * 8 + 2 * q;
            if (MODE == 0) {
                size_t zi = (size_t)(m0 + mlo) * HH + n0 + n;
                *(float2*)(g_Z + zi) =
                    make_float2(acc[f][bt][0] + bs0[bt], acc[f][bt][1] + bs1[bt]);
                *(float2*)(g_Z + zi + (size_t)8 * HH) =
                    make_float2(acc[f][bt][2] + bs0[bt], acc[f][bt][3] + bs1[bt]);
            } else {
                size_t oi = (size_t)(m0 + mlo) * OO + n0 + n;
                *(float2*)(outp + oi) =
                    make_float2(sigf(acc[f][bt][0] + bs0[bt]), sigf(acc[f][bt][1] + bs1[bt]));
                *(float2*)(outp + oi + (size_t)8 * OO) =
                    make_float2(sigf(acc[f][bt][2] + bs0[bt]), sigf(acc[f][bt][3] + bs1[bt]));
            }
        }
    }
}

// ---------------- persistent recurrence: aa ONLY, 128 CTAs, dataflow flags -------
// Chunk c = contiguous cols [256c, +256) of a_it -> produced by slice group c
// (slices 8c..8c+7 of the same mh). Consumer polls flag[mh][c] >= it*8 just
// before loading chunk c: no global barrier, CTA spread absorbed per-group.
// 8 warps: warp w handles cols [256c+32w, +32) of each chunk; full m32 x n32
// tile per warp = 8 accumulator chains. Ring-3, depth-2 prefetch.
#define NCTA_R 128
#define WPAD 2056
#define NCH 8
#define ASTR 264                                     // 256 + 8 pad
#define ABUFH (32 * ASTR)                            // 8448 halves = 16896 B
#define ZSTR 36
#define OFF_W 0
#define OFF_A (32 * WPAD * 2)                        // 131584
#define OFF_RED (OFF_A + 3 * ABUFH * 2)              // 131584 + 50688 = 182272
#define OFF_Z (OFF_RED + 8 * 32 * 32 * 4)            // + 32768 = 215040
#define PERS_SMEM (OFF_Z + 2 * 32 * ZSTR * 4)        // + 9216 = 224256

__global__ void __launch_bounds__(256) rnn_persistent() {
    extern __shared__ __align__(16) unsigned char smraw[];
    __half* Wsm = (__half*)(smraw + OFF_W);        // [32][WPAD]
    __half* Asm = (__half*)(smraw + OFF_A);        // [3][32][ASTR]
    float*  red = (float*)(smraw + OFF_RED);       // [8 w][32][32]
    float*  Zsm = (float*)(smraw + OFF_Z);         // [2][32][ZSTR]

    const int tid = threadIdx.x;
    const int lane = tid & 31, warp = tid >> 5;
    const int cta = blockIdx.x;
    const int slice = cta & 63;
    const int mh = cta >> 6;                 // 0..1
    const int n0 = slice * 32;
    const int row0 = mh * 32;
    unsigned* flags = &g_barh[(size_t)mh * 8 * 32];  // flag g at flags[g*32]
    unsigned* myflag = &g_barh[((size_t)mh * 8 + (slice >> 3)) * 32];

    // Z slice loader: 32 rows x 32 floats = 256 16B segs, 1/thread
    auto loadZ = [&](int it, int zb) {
        int row = tid >> 3, j = tid & 7;
        cp_async16(Zsm + zb * (32 * ZSTR) + row * ZSTR + j * 4,
                   g_Z + ((size_t)it * 64 + row0 + row) * HH + n0 + j * 4);
    };

    // persistent W_aa slice: 32 rows x 2048 halves; plus Z for step 0
    for (int u = tid; u < 32 * 256; u += 256) {
        int row = u >> 8, cg = u & 255;
        cp_async16(Wsm + row * WPAD + cg * 8, g_Waa + (size_t)(n0 + row) * HH + cg * 8);
    }
    loadZ(0, 0);
    cp_commit();
    cp_wait0();
    __syncthreads();

    const int wq = warp;               // 0..7: 32-col sub-block within each chunk
    const int gr = lane >> 2, q = lane & 3;
    const int arow = ((lane >> 3) & 1) * 8 + (lane & 7);
    const int akoff = (lane >> 4) * 8;
    const int brow = (lane >> 4) * 8 + (lane & 7);
    const int bkoff = ((lane >> 3) & 1) * 8;

    // chunk loader: 32 rows x 256 contiguous cols = 1024 16B segs, 4/thread
    auto loadA = [&](int buf, int c, const __half* a_src) {
#pragma unroll
        for (int r = 0; r < 4; ++r) {
            int idx = tid + r * 256;
            int row = idx >> 5, seg = idx & 31;
            cp_async16(Asm + buf * ABUFH + row * ASTR + seg * 8,
                       a_src + (size_t)(row0 + row) * HH + c * 256 + seg * 8);
        }
    };

    // epilogue indices: thread handles 4 consecutive cols of one row
    const int erow = tid >> 3;            // 0..31
    const int ecol = (tid & 7) * 4;       // 0,4,..,28

    for (int it = 0; it < TT; ++it) {
        const __half* a_cur = g_ahist + (size_t)it * NA0;
        const float* Zb = Zsm + (it & 1) * (32 * ZSTR);
        const unsigned tgt = (unsigned)it * 8u;

        float acc[2][4][4];
#pragma unroll
        for (int f = 0; f < 2; ++f)
#pragma unroll
            for (int bs = 0; bs < 4; ++bs)
#pragma unroll
                for (int c = 0; c < 4; ++c) acc[f][bs][c] = 0.0f;

        // wait for producer groups 0,1 then prologue loads
        if (tid == 0) {
            while (ld_acq(&flags[0]) < tgt) { }
            while (ld_acq(&flags[32]) < tgt) { }
        }
        __syncthreads();
        loadA(0, 0, a_cur); cp_commit();
        loadA(1, 1, a_cur); cp_commit();

        for (int c = 0; c < NCH; ++c) {
            // ensure producer group c+2 has published before loading its chunk
            if (tid == 0 && c + 2 < NCH) {
                while (ld_acq(&flags[(c + 2) * 32]) < tgt) { }
            }
            if (c < NCH - 1) cp_wait1(); else cp_wait0();
            __syncthreads();   // chunk c resident; flag observed; buffer free
            if (c + 2 < NCH) { loadA((c + 2) % 3, c + 2, a_cur); cp_commit(); }

            const __half* Ab = Asm + (c % 3) * ABUFH;
#pragma unroll
            for (int s = 0; s < 2; ++s) {
                uint32_t a[2][4];
#pragma unroll
                for (int f = 0; f < 2; ++f)
                    ldsm4(a[f][0], a[f][1], a[f][2], a[f][3],
                          Ab + (f * 16 + arow) * ASTR + wq * 32 + s * 16 + akoff);
                int bcol = c * 256 + wq * 32 + s * 16 + bkoff;
                uint32_t bl0, bl1, bl2, bl3, bu0, bu1, bu2, bu3;
                ldsm4(bl0, bl1, bl2, bl3, Wsm + brow * WPAD + bcol);
                ldsm4(bu0, bu1, bu2, bu3, Wsm + (brow + 16) * WPAD + bcol);
#pragma unroll
                for (int f = 0; f < 2; ++f) {
                    mma16816(acc[f][0], a[f], bl0, bl1);
                    mma16816(acc[f][1], a[f], bl2, bl3);
                    mma16816(acc[f][2], a[f], bu0, bu1);
                    mma16816(acc[f][3], a[f], bu2, bu3);
                }
            }
        }

        // ---- all warps write partials ----
        {
            float* rp = red + (size_t)wq * 1024;
#pragma unroll
            for (int f = 0; f < 2; ++f)
#pragma unroll
                for (int bs = 0; bs < 4; ++bs) {
                    int row = f * 16 + gr, col = bs * 8 + 2 * q;
                    *(float2*)(rp + row * 32 + col) = make_float2(acc[f][bs][0], acc[f][bs][1]);
                    *(float2*)(rp + (row + 8) * 32 + col) = make_float2(acc[f][bs][2], acc[f][bs][3]);
                }
        }
        __syncthreads();

        // ---- distributed reduce + sigmoid + store (4 outputs/thread) ----
        {
            float4 sum = *(const float4*)(red + (size_t)erow * 32 + ecol);
#pragma unroll
            for (int p = 1; p < 8; ++p) {
                float4 v = *(const float4*)(red + (size_t)p * 1024 + erow * 32 + ecol);
                sum.x += v.x; sum.y += v.y; sum.z += v.z; sum.w += v.w;
            }
            float4 z = *(const float4*)(Zb + erow * ZSTR + ecol);
            __half2 h0 = __floats2half2_rn(sigf(sum.x + z.x), sigf(sum.y + z.y));
            __half2 h1 = __floats2half2_rn(sigf(sum.z + z.z), sigf(sum.w + z.w));
            __half* adst = g_ahist + (size_t)(it + 1) * NA0
                         + (size_t)(row0 + erow) * HH + n0 + ecol;
            *(uint2*)adst = make_uint2(*(uint32_t*)&h0, *(uint32_t*)&h1);
        }

        // prefetch next step's Z (g_Z is static)
        if (it + 1 < TT) { loadZ(it + 1, (it + 1) & 1); cp_commit(); }

        // publish a_{it+1} for this slice's group
        __syncthreads();                 // all stores of this CTA complete
        if (tid == 0) red_rel_add1(myflag);
    }
}

// ---------------- launch ----------------
extern "C" void kernel_launch(void* const* d_in, const int* in_sizes, int n_in,
                              void* d_out, int out_size) {
    const float* x    = (const float*)d_in[0];
    const float* Waa  = (const float*)d_in[1];
    const float* b_aa = (const float*)d_in[2];
    const float* Wax  = (const float*)d_in[3];
    const float* b_ax = (const float*)d_in[4];
    const float* Wya  = (const float*)d_in[5];
    const float* b_ya = (const float*)d_in[6];
    float* out = (float*)d_out;

    static bool attr_done = false;
    if (!attr_done) {
        cudaFuncSetAttribute(big_gemm<0>, cudaFuncAttributeMaxDynamicSharedMemorySize, XP_SMEM);
        cudaFuncSetAttribute(big_gemm<1>, cudaFuncAttributeMaxDynamicSharedMemorySize, XP_SMEM);
        cudaFuncSetAttribute(rnn_persistent, cudaFuncAttributeMaxDynamicSharedMemorySize, PERS_SMEM);
        attr_done = true;
    }

    int prep_blocks = (int)((NPREP4 + 255) / 256);
    prep_kernel<<<prep_blocks, 256>>>(x, Waa, Wax, Wya);

    dim3 xg(HH / 128, (TT * BB) / 128);   // 16 x 128
    big_gemm<0><<<xg, 256, XP_SMEM>>>(b_ax, b_aa, nullptr);

    rnn_persistent<<<NCTA_R, 256, PERS_SMEM>>>();

    dim3 yg(OO / 128, (TT * BB) / 128);   // 8 x 128
    big_gemm<1><<<yg, 256, XP_SMEM>>>(b_ya, nullptr, out);
}

// round 16
// speedup vs baseline: 1.4710x; 1.4710x over previous
#include <cuda_runtime.h>
#include <cuda_fp16.h>
#include <cstdint>

#define BB 64
#define TT 256
#define II 1024
#define HH 2048
#define OO 1024

// ---------------- device scratch ----------------
__device__ __half g_xh[(size_t)BB * TT * II];
__device__ __half g_Wax[(size_t)HH * II];
__device__ __half g_Waa[(size_t)HH * HH];
__device__ __half g_Wya[(size_t)OO * HH];
__device__ float  g_Z[(size_t)TT * BB * HH];                 // x W_ax^T + b_ax + b_aa
__device__ __half g_ahist[(size_t)(TT + 1) * BB * HH];       // all hidden states
__device__ unsigned g_barh[512];                              // [(mh*8+g)*32]: group counters

// ---------------- helpers ----------------
__device__ __forceinline__ uint32_t sptr(const void* p) {
    return (uint32_t)__cvta_generic_to_shared(p);
}
__device__ __forceinline__ void cp_async16(const void* dst_smem, const void* src) {
    asm volatile("cp.async.cg.shared.global [%0], [%1], 16;"
                 :: "r"(sptr(dst_smem)), "l"(src));
}
__device__ __forceinline__ void cp_commit() { asm volatile("cp.async.commit_group;"); }
__device__ __forceinline__ void cp_wait0()  { asm volatile("cp.async.wait_group 0;"); }
__device__ __forceinline__ void cp_wait1()  { asm volatile("cp.async.wait_group 1;"); }

__device__ __forceinline__ void ldsm4(uint32_t& r0, uint32_t& r1, uint32_t& r2, uint32_t& r3,
                                      const void* p) {
    asm volatile("ldmatrix.sync.aligned.m8n8.x4.shared.b16 {%0,%1,%2,%3},[%4];"
                 : "=r"(r0), "=r"(r1), "=r"(r2), "=r"(r3) : "r"(sptr(p)));
}
__device__ __forceinline__ void mma16816(float* c, const uint32_t* a,
                                         uint32_t b0, uint32_t b1) {
    asm volatile("mma.sync.aligned.m16n8k16.row.col.f32.f16.f16.f32 "
                 "{%0,%1,%2,%3},{%4,%5,%6,%7},{%8,%9},{%0,%1,%2,%3};"
                 : "+f"(c[0]), "+f"(c[1]), "+f"(c[2]), "+f"(c[3])
                 : "r"(a[0]), "r"(a[1]), "r"(a[2]), "r"(a[3]), "r"(b0), "r"(b1));
}
__device__ __forceinline__ float sigf(float v) { return 1.0f / (1.0f + __expf(-v)); }

__device__ __forceinline__ unsigned ld_acq(const unsigned* p) {
    unsigned v;
    asm volatile("ld.acquire.gpu.u32 %0, [%1];" : "=r"(v) : "l"(p));
    return v;
}
__device__ __forceinline__ void red_rel_add1(unsigned* p) {
    asm volatile("red.release.gpu.add.u32 [%0], 1;" :: "l"(p));
}

// ---------------- prep (vectorized x4) ----------------
#define NX  ((size_t)BB * TT * II)
#define NAA ((size_t)HH * HH)
#define NAX ((size_t)HH * II)
#define NYA ((size_t)OO * HH)
#define NA0 ((size_t)BB * HH)
#define NPREP4 ((NX + NAA + NAX + NYA + NA0) / 4)

__device__ __forceinline__ void cvt4(__half* dst, const float* src, size_t i4) {
    float4 v = *(const float4*)(src + i4 * 4);
    __half2 h0 = __floats2half2_rn(v.x, v.y);
    __half2 h1 = __floats2half2_rn(v.z, v.w);
    *(uint2*)(dst + i4 * 4) = make_uint2(*(uint32_t*)&h0, *(uint32_t*)&h1);
}

__global__ void prep_kernel(const float* __restrict__ x, const float* __restrict__ Waa,
                            const float* __restrict__ Wax, const float* __restrict__ Wya) {
    size_t i = (size_t)blockIdx.x * blockDim.x + threadIdx.x;
    if (i < 512) g_barh[i] = 0u;
    if (i < NX / 4) { cvt4(g_xh, x, i); return; }
    i -= NX / 4;
    if (i < NAA / 4) { cvt4(g_Waa, Waa, i); return; }
    i -= NAA / 4;
    if (i < NAX / 4) { cvt4(g_Wax, Wax, i); return; }
    i -= NAX / 4;
    if (i < NYA / 4) { cvt4(g_Wya, Wya, i); return; }
    i -= NYA / 4;
    if (i < NA0 / 4) { *(uint2*)(g_ahist + i * 4) = make_uint2(0u, 0u); }  // a_0 = 0
}

// ---------------- big parallel GEMM (xproj MODE 0 / ypass MODE 1) ----------------
#define XP_SMEM (2 * (2 * 128 * 72 * 2))

template <int MODE>
__global__ void __launch_bounds__(256) big_gemm(const float* __restrict__ c0,
                                                const float* __restrict__ c1,
                                                float* __restrict__ outp) {
    constexpr int KD = (MODE == 0) ? II : HH;
    constexpr int NCHX = KD / 64;
    extern __shared__ __align__(16) unsigned char smraw[];
    __half* As = (__half*)smraw;                       // [2][128][72]
    __half* Bs = (__half*)(smraw + 2 * 128 * 72 * 2);  // [2][128][72]

    const int tid = threadIdx.x;
    const int lane = tid & 31, warp = tid >> 5;
    const int n0 = blockIdx.x * 128;
    const int m0 = blockIdx.y * 128;
    const int wm = (warp >> 1) * 32;
    const int wn = (warp & 1) * 64;
    const int gr = lane >> 2, q = lane & 3;

    const int arow = ((lane >> 3) & 1) * 8 + (lane & 7);
    const int akoff = (lane >> 4) * 8;
    const int brow = (lane >> 4) * 8 + (lane & 7);
    const int bkoff = ((lane >> 3) & 1) * 8;

    const __half* Wg = (MODE == 0) ? g_Wax : g_Wya;

    float acc[2][8][4];
#pragma unroll
    for (int f = 0; f < 2; ++f)
#pragma unroll
        for (int bt = 0; bt < 8; ++bt)
#pragma unroll
            for (int c = 0; c < 4; ++c) acc[f][bt][c] = 0.0f;

    auto load_chunk = [&](int buf, int ck) {
#pragma unroll
        for (int r = 0; r < 4; ++r) {
            int u = tid + r * 256;
            int row = u >> 3, cg = u & 7;
            int m = m0 + row;
            const __half* asrc;
            if (MODE == 0) {
                int t = m >> 6, b = m & 63;
                asrc = g_xh + ((size_t)b * TT + t) * II + ck * 64 + cg * 8;
            } else {
                asrc = g_ahist + (size_t)(m + 64) * HH + ck * 64 + cg * 8;
            }
            cp_async16(As + buf * (128 * 72) + row * 72 + cg * 8, asrc);
            cp_async16(Bs + buf * (128 * 72) + row * 72 + cg * 8,
                       Wg + (size_t)(n0 + row) * KD + ck * 64 + cg * 8);
        }
    };

    load_chunk(0, 0);
    cp_commit();
    for (int ck = 0; ck < NCHX; ++ck) {
        if (ck + 1 < NCHX) { load_chunk((ck + 1) & 1, ck + 1); cp_commit(); cp_wait1(); }
        else cp_wait0();
        __syncthreads();
        const __half* Ab = As + (ck & 1) * (128 * 72);
        const __half* Bb = Bs + (ck & 1) * (128 * 72);
#pragma unroll
        for (int s = 0; s < 4; ++s) {
            uint32_t a[2][4];
#pragma unroll
            for (int f = 0; f < 2; ++f)
                ldsm4(a[f][0], a[f][1], a[f][2], a[f][3],
                      Ab + (wm + f * 16 + arow) * 72 + s * 16 + akoff);
#pragma unroll
            for (int bp = 0; bp < 4; ++bp) {
                uint32_t b0, b1, b2, b3;
                ldsm4(b0, b1, b2, b3,
                      Bb + (wn + bp * 16 + brow) * 72 + s * 16 + bkoff);
#pragma unroll
                for (int f = 0; f < 2; ++f) {
                    mma16816(acc[f][2 * bp],     a[f], b0, b1);
                    mma16816(acc[f][2 * bp + 1], a[f], b2, b3);
                }
            }
        }
        __syncthreads();
    }

    float bs0[8], bs1[8];
#pragma unroll
    for (int bt = 0; bt < 8; ++bt) {
        int n = n0 + wn + bt * 8 + 2 * q;
        if (MODE == 0) { bs0[bt] = c0[n] + c1[n]; bs1[bt] = c0[n + 1] + c1[n + 1]; }
        else           { bs0[bt] = c0[n];         bs1[bt] = c0[n + 1]; }
    }
#pragma unroll
    for (int f = 0; f < 2; ++f) {
#pragma unroll
        for (int bt = 0; bt < 8; ++bt) {
            int mlo = wm + f * 16 + gr;
            int n = wn + bt * 8 + 2 * q;
            if (MODE == 0) {
                size_t zi = (size_t)(m0 + mlo) * HH + n0 + n;
                *(float2*)(g_Z + zi) =
                    make_float2(acc[f][bt][0] + bs0[bt], acc[f][bt][1] + bs1[bt]);
                *(float2*)(g_Z + zi + (size_t)8 * HH) =
                    make_float2(acc[f][bt][2] + bs0[bt], acc[f][bt][3] + bs1[bt]);
            } else {
                size_t oi = (size_t)(m0 + mlo) * OO + n0 + n;
                *(float2*)(outp + oi) =
                    make_float2(sigf(acc[f][bt][0] + bs0[bt]), sigf(acc[f][bt][1] + bs1[bt]));
                *(float2*)(outp + oi + (size_t)8 * OO) =
                    make_float2(sigf(acc[f][bt][2] + bs0[bt]), sigf(acc[f][bt][3] + bs1[bt]));
            }
        }
    }
}

// ---------------- persistent recurrence: aa ONLY, 128 CTAs --------------------
// Warp w owns k-eighth [256w,+256) of a_it -> produced ENTIRELY by slice group w
// (slices 8w..8w+7, same mh). Per-warp dataflow: warp w polls ONLY flag[w] once
// per step (8 polls in parallel), then runs its private cp.async ring (3 bufs of
// 32x32 cols) with NO block syncs in the mainloop. CTA syncs only at reduction
// and publish. Z single-buffered, loaded at step start (needed only at epilogue).
#define NCTA_R 128
#define WPAD 2056
#define NCH 8
#define AWSTR 40                                     // 32 + 8 pad (16B-aligned rows)
#define AWBUF (32 * AWSTR)                           // 1280 halves per buffer
#define AWRING (3 * AWBUF)                           // 3840 halves = 7680 B per warp
#define ZSTR 36
#define OFF_W 0
#define OFF_A (32 * WPAD * 2)                        // 131584
#define OFF_RED (OFF_A + 8 * AWRING * 2)             // 131584 + 61440 = 193024
#define OFF_Z (OFF_RED + 8 * 32 * 32 * 4)            // + 32768 = 225792
#define PERS_SMEM (OFF_Z + 32 * ZSTR * 4)            // + 4608 = 230400

__global__ void __launch_bounds__(256) rnn_persistent() {
    extern __shared__ __align__(16) unsigned char smraw[];
    __half* Wsm = (__half*)(smraw + OFF_W);        // [32][WPAD]
    __half* Asm = (__half*)(smraw + OFF_A);        // [8 w][3][32][AWSTR]
    float*  red = (float*)(smraw + OFF_RED);       // [8 w][32][32]
    float*  Zsm = (float*)(smraw + OFF_Z);         // [32][ZSTR]

    const int tid = threadIdx.x;
    const int lane = tid & 31, warp = tid >> 5;
    const int cta = blockIdx.x;
    const int slice = cta & 63;
    const int mh = cta >> 6;                 // 0..1
    const int n0 = slice * 32;
    const int row0 = mh * 32;
    const unsigned* myWflag = &g_barh[((size_t)mh * 8 + warp) * 32];   // warp's producer
    unsigned* myflag = &g_barh[((size_t)mh * 8 + (slice >> 3)) * 32];  // this CTA's group

    // Z slice loader: 32 rows x 32 floats = 256 16B segs, 1/thread
    auto loadZ = [&](int it) {
        int row = tid >> 3, j = tid & 7;
        cp_async16(Zsm + row * ZSTR + j * 4,
                   g_Z + ((size_t)it * 64 + row0 + row) * HH + n0 + j * 4);
    };

    // persistent W_aa slice: 32 rows x 2048 halves
    for (int u = tid; u < 32 * 256; u += 256) {
        int row = u >> 8, cg = u & 255;
        cp_async16(Wsm + row * WPAD + cg * 8, g_Waa + (size_t)(n0 + row) * HH + cg * 8);
    }
    cp_commit();
    cp_wait0();
    __syncthreads();

    const int gr = lane >> 2, q = lane & 3;
    const int arow = ((lane >> 3) & 1) * 8 + (lane & 7);
    const int akoff = (lane >> 4) * 8;
    const int brow = (lane >> 4) * 8 + (lane & 7);
    const int bkoff = ((lane >> 3) & 1) * 8;

    __half* Aw = Asm + (size_t)warp * AWRING;    // this warp's private ring

    // per-warp chunk loader: 32 rows x 32 cols = 128 16B segs, 4/lane
    auto loadA = [&](int buf, int c, const __half* a_src) {
#pragma unroll
        for (int r = 0; r < 4; ++r) {
            int idx = lane + r * 32;
            int row = idx >> 2, j = idx & 3;
            cp_async16(Aw + buf * AWBUF + row * AWSTR + j * 8,
                       a_src + (size_t)(row0 + row) * HH + warp * 256 + c * 32 + j * 8);
        }
    };

    // epilogue indices: thread handles 4 consecutive cols of one row
    const int erow = tid >> 3;            // 0..31
    const int ecol = (tid & 7) * 4;       // 0,4,..,28

    for (int it = 0; it < TT; ++it) {
        const __half* a_cur = g_ahist + (size_t)it * NA0;
        const unsigned tgt = (unsigned)it * 8u;

        float acc[2][4][4];
#pragma unroll
        for (int f = 0; f < 2; ++f)
#pragma unroll
            for (int bs = 0; bs < 4; ++bs)
#pragma unroll
                for (int c = 0; c < 4; ++c) acc[f][bs][c] = 0.0f;

        // warp-local producer wait (8 polls run in parallel across warps)
        if (lane == 0) {
            while (ld_acq(myWflag) < tgt) { }
        }
        __syncwarp();

        // prologue: Z (step-start, consumed only at epilogue) + chunks 0,1
        loadZ(it);
        loadA(0, 0, a_cur); cp_commit();
        loadA(1, 1, a_cur); cp_commit();

        for (int c = 0; c < NCH; ++c) {
            if (c < NCH - 1) cp_wait1(); else cp_wait0();
            // per-warp ring: buffer (c+2)%3 was consumed by THIS warp at c-1
            if (c + 2 < NCH) { loadA((c + 2) % 3, c + 2, a_cur); cp_commit(); }

            const __half* Ab = Aw + (c % 3) * AWBUF;
#pragma unroll
            for (int s = 0; s < 2; ++s) {
                uint32_t a[2][4];
#pragma unroll
                for (int f = 0; f < 2; ++f)
                    ldsm4(a[f][0], a[f][1], a[f][2], a[f][3],
                          Ab + (f * 16 + arow) * AWSTR + s * 16 + akoff);
                int bcol = warp * 256 + c * 32 + s * 16 + bkoff;
                uint32_t bl0, bl1, bl2, bl3, bu0, bu1, bu2, bu3;
                ldsm4(bl0, bl1, bl2, bl3, Wsm + brow * WPAD + bcol);
                ldsm4(bu0, bu1, bu2, bu3, Wsm + (brow + 16) * WPAD + bcol);
#pragma unroll
                for (int f = 0; f < 2; ++f) {
                    mma16816(acc[f][0], a[f], bl0, bl1);
                    mma16816(acc[f][1], a[f], bl2, bl3);
                    mma16816(acc[f][2], a[f], bu0, bu1);
                    mma16816(acc[f][3], a[f], bu2, bu3);
                }
            }
        }

        // ---- write partials (own region, no sync needed before) ----
        {
            float* rp = red + (size_t)warp * 1024;
#pragma unroll
            for (int f = 0; f < 2; ++f)
#pragma unroll
                for (int bs = 0; bs < 4; ++bs) {
                    int row = f * 16 + gr, col = bs * 8 + 2 * q;
                    *(float2*)(rp + row * 32 + col) = make_float2(acc[f][bs][0], acc[f][bs][1]);
                    *(float2*)(rp + (row + 8) * 32 + col) = make_float2(acc[f][bs][2], acc[f][bs][3]);
                }
        }
        __syncthreads();   // all warps' partials + Z visible

        // ---- distributed reduce + sigmoid + store (4 outputs/thread) ----
        {
            float4 sum = *(const float4*)(red + (size_t)erow * 32 + ecol);
#pragma unroll
            for (int p = 1; p < 8; ++p) {
                float4 v = *(const float4*)(red + (size_t)p * 1024 + erow * 32 + ecol);
                sum.x += v.x; sum.y += v.y; sum.z += v.z; sum.w += v.w;
            }
            float4 z = *(const float4*)(Zsm + erow * ZSTR + ecol);
            __half2 h0 = __floats2half2_rn(sigf(sum.x + z.x), sigf(sum.y + z.y));
            __half2 h1 = __floats2half2_rn(sigf(sum.z + z.z), sigf(sum.w + z.w));
            __half* adst = g_ahist + (size_t)(it + 1) * NA0
                         + (size_t)(row0 + erow) * HH + n0 + ecol;
            *(uint2*)adst = make_uint2(*(uint32_t*)&h0, *(uint32_t*)&h1);
        }

        // publish a_{it+1} for this slice's group
        __syncthreads();                 // all stores of this CTA complete
        if (tid == 0) red_rel_add1(myflag);
    }
}

// ---------------- launch ----------------
extern "C" void kernel_launch(void* const* d_in, const int* in_sizes, int n_in,
                              void* d_out, int out_size) {
    const float* x    = (const float*)d_in[0];
    const float* Waa  = (const float*)d_in[1];
    const float* b_aa = (const float*)d_in[2];
    const float* Wax  = (const float*)d_in[3];
    const float* b_ax = (const float*)d_in[4];
    const float* Wya  = (const float*)d_in[5];
    const float* b_ya = (const float*)d_in[6];
    float* out = (float*)d_out;

    static bool attr_done = false;
    if (!attr_done) {
        cudaFuncSetAttribute(big_gemm<0>, cudaFuncAttributeMaxDynamicSharedMemorySize, XP_SMEM);
        cudaFuncSetAttribute(big_gemm<1>, cudaFuncAttributeMaxDynamicSharedMemorySize, XP_SMEM);
        cudaFuncSetAttribute(rnn_persistent, cudaFuncAttributeMaxDynamicSharedMemorySize, PERS_SMEM);
        attr_done = true;
    }

    int prep_blocks = (int)((NPREP4 + 255) / 256);
    prep_kernel<<<prep_blocks, 256>>>(x, Waa, Wax, Wya);

    dim3 xg(HH / 128, (TT * BB) / 128);   // 16 x 128
    big_gemm<0><<<xg, 256, XP_SMEM>>>(b_ax, b_aa, nullptr);

    rnn_persistent<<<NCTA_R, 256, PERS_SMEM>>>();

    dim3 yg(OO / 128, (TT * BB) / 128);   // 8 x 128
    big_gemm<1><<<yg, 256, XP_SMEM>>>(b_ya, nullptr, out);
}

// round 17
// speedup vs baseline: 1.4740x; 1.0020x over previous
#include <cuda_runtime.h>
#include <cuda_fp16.h>
#include <cstdint>

#define BB 64
#define TT 256
#define II 1024
#define HH 2048
#define OO 1024

// ---------------- device scratch ----------------
__device__ __half g_xh[(size_t)BB * TT * II];
__device__ __half g_Wax[(size_t)HH * II];
__device__ __half g_Waa[(size_t)HH * HH];
__device__ __half g_Wya[(size_t)OO * HH];
__device__ float  g_Z[(size_t)TT * BB * HH];                 // x W_ax^T + b_ax + b_aa
__device__ __half g_ahist[(size_t)(TT + 1) * BB * HH];       // all hidden states
__device__ unsigned g_barh[512];                              // [(mh*8+g)*32]: group counters

// ---------------- helpers ----------------
__device__ __forceinline__ uint32_t sptr(const void* p) {
    return (uint32_t)__cvta_generic_to_shared(p);
}
__device__ __forceinline__ void cp_async16(const void* dst_smem, const void* src) {
    asm volatile("cp.async.cg.shared.global [%0], [%1], 16;"
                 :: "r"(sptr(dst_smem)), "l"(src));
}
__device__ __forceinline__ void cp_commit() { asm volatile("cp.async.commit_group;"); }
__device__ __forceinline__ void cp_wait0()  { asm volatile("cp.async.wait_group 0;"); }
__device__ __forceinline__ void cp_wait1()  { asm volatile("cp.async.wait_group 1;"); }

__device__ __forceinline__ void ldsm4(uint32_t& r0, uint32_t& r1, uint32_t& r2, uint32_t& r3,
                                      const void* p) {
    asm volatile("ldmatrix.sync.aligned.m8n8.x4.shared.b16 {%0,%1,%2,%3},[%4];"
                 : "=r"(r0), "=r"(r1), "=r"(r2), "=r"(r3) : "r"(sptr(p)));
}
__device__ __forceinline__ void mma16816(float* c, const uint32_t* a,
                                         uint32_t b0, uint32_t b1) {
    asm volatile("mma.sync.aligned.m16n8k16.row.col.f32.f16.f16.f32 "
                 "{%0,%1,%2,%3},{%4,%5,%6,%7},{%8,%9},{%0,%1,%2,%3};"
                 : "+f"(c[0]), "+f"(c[1]), "+f"(c[2]), "+f"(c[3])
                 : "r"(a[0]), "r"(a[1]), "r"(a[2]), "r"(a[3]), "r"(b0), "r"(b1));
}
__device__ __forceinline__ float sigf(float v) { return 1.0f / (1.0f + __expf(-v)); }

__device__ __forceinline__ unsigned ld_acq(const unsigned* p) {
    unsigned v;
    asm volatile("ld.acquire.gpu.u32 %0, [%1];" : "=r"(v) : "l"(p));
    return v;
}
__device__ __forceinline__ void red_rel_add1(unsigned* p) {
    asm volatile("red.release.gpu.add.u32 [%0], 1;" :: "l"(p));
}

// ---------------- prep (vectorized x4) ----------------
#define NX  ((size_t)BB * TT * II)
#define NAA ((size_t)HH * HH)
#define NAX ((size_t)HH * II)
#define NYA ((size_t)OO * HH)
#define NA0 ((size_t)BB * HH)
#define NPREP4 ((NX + NAA + NAX + NYA + NA0) / 4)

__device__ __forceinline__ void cvt4(__half* dst, const float* src, size_t i4) {
    float4 v = *(const float4*)(src + i4 * 4);
    __half2 h0 = __floats2half2_rn(v.x, v.y);
    __half2 h1 = __floats2half2_rn(v.z, v.w);
    *(uint2*)(dst + i4 * 4) = make_uint2(*(uint32_t*)&h0, *(uint32_t*)&h1);
}

__global__ void prep_kernel(const float* __restrict__ x, const float* __restrict__ Waa,
                            const float* __restrict__ Wax, const float* __restrict__ Wya) {
    size_t i = (size_t)blockIdx.x * blockDim.x + threadIdx.x;
    if (i < 512) g_barh[i] = 0u;
    if (i < NX / 4) { cvt4(g_xh, x, i); return; }
    i -= NX / 4;
    if (i < NAA / 4) { cvt4(g_Waa, Waa, i); return; }
    i -= NAA / 4;
    if (i < NAX / 4) { cvt4(g_Wax, Wax, i); return; }
    i -= NAX / 4;
    if (i < NYA / 4) { cvt4(g_Wya, Wya, i); return; }
    i -= NYA / 4;
    if (i < NA0 / 4) { *(uint2*)(g_ahist + i * 4) = make_uint2(0u, 0u); }  // a_0 = 0
}

// ---------------- big parallel GEMM (xproj MODE 0 / ypass MODE 1) ----------------
// Ring-3 buffers, depth-2 cp.async prefetch, ONE __syncthreads per k-chunk.
#define XPB (128 * 72)                     // halves per buffer plane
#define XP_SMEM (2 * (3 * XPB * 2))        // As[3] + Bs[3] = 110592 B

template <int MODE>
__global__ void __launch_bounds__(256) big_gemm(const float* __restrict__ c0,
                                                const float* __restrict__ c1,
                                                float* __restrict__ outp) {
    constexpr int KD = (MODE == 0) ? II : HH;
    constexpr int NCHX = KD / 64;
    extern __shared__ __align__(16) unsigned char smraw[];
    __half* As = (__half*)smraw;                     // [3][128][72]
    __half* Bs = (__half*)(smraw + 3 * XPB * 2);     // [3][128][72]

    const int tid = threadIdx.x;
    const int lane = tid & 31, warp = tid >> 5;
    const int n0 = blockIdx.x * 128;
    const int m0 = blockIdx.y * 128;
    const int wm = (warp >> 1) * 32;
    const int wn = (warp & 1) * 64;
    const int gr = lane >> 2, q = lane & 3;

    const int arow = ((lane >> 3) & 1) * 8 + (lane & 7);
    const int akoff = (lane >> 4) * 8;
    const int brow = (lane >> 4) * 8 + (lane & 7);
    const int bkoff = ((lane >> 3) & 1) * 8;

    const __half* Wg = (MODE == 0) ? g_Wax : g_Wya;

    float acc[2][8][4];
#pragma unroll
    for (int f = 0; f < 2; ++f)
#pragma unroll
        for (int bt = 0; bt < 8; ++bt)
#pragma unroll
            for (int c = 0; c < 4; ++c) acc[f][bt][c] = 0.0f;

    auto load_chunk = [&](int buf, int ck) {
#pragma unroll
        for (int r = 0; r < 4; ++r) {
            int u = tid + r * 256;
            int row = u >> 3, cg = u & 7;
            int m = m0 + row;
            const __half* asrc;
            if (MODE == 0) {
                int t = m >> 6, b = m & 63;
                asrc = g_xh + ((size_t)b * TT + t) * II + ck * 64 + cg * 8;
            } else {
                asrc = g_ahist + (size_t)(m + 64) * HH + ck * 64 + cg * 8;
            }
            cp_async16(As + buf * XPB + row * 72 + cg * 8, asrc);
            cp_async16(Bs + buf * XPB + row * 72 + cg * 8,
                       Wg + (size_t)(n0 + row) * KD + ck * 64 + cg * 8);
        }
    };

    load_chunk(0, 0); cp_commit();
    load_chunk(1, 1); cp_commit();

    for (int ck = 0; ck < NCHX; ++ck) {
        if (ck < NCHX - 1) cp_wait1(); else cp_wait0();
        __syncthreads();   // chunk ck resident; all warps done with ck-1
        if (ck + 2 < NCHX) { load_chunk((ck + 2) % 3, ck + 2); cp_commit(); }

        const __half* Ab = As + (ck % 3) * XPB;
        const __half* Bb = Bs + (ck % 3) * XPB;
#pragma unroll
        for (int s = 0; s < 4; ++s) {
            uint32_t a[2][4];
#pragma unroll
            for (int f = 0; f < 2; ++f)
                ldsm4(a[f][0], a[f][1], a[f][2], a[f][3],
                      Ab + (wm + f * 16 + arow) * 72 + s * 16 + akoff);
#pragma unroll
            for (int bp = 0; bp < 4; ++bp) {
                uint32_t b0, b1, b2, b3;
                ldsm4(b0, b1, b2, b3,
                      Bb + (wn + bp * 16 + brow) * 72 + s * 16 + bkoff);
#pragma unroll
                for (int f = 0; f < 2; ++f) {
                    mma16816(acc[f][2 * bp],     a[f], b0, b1);
                    mma16816(acc[f][2 * bp + 1], a[f], b2, b3);
                }
            }
        }
    }

    float bs0[8], bs1[8];
#pragma unroll
    for (int bt = 0; bt < 8; ++bt) {
        int n = n0 + wn + bt * 8 + 2 * q;
        if (MODE == 0) { bs0[bt] = c0[n] + c1[n]; bs1[bt] = c0[n + 1] + c1[n + 1]; }
        else           { bs0[bt] = c0[n];         bs1[bt] = c0[n + 1]; }
    }
#pragma unroll
    for (int f = 0; f < 2; ++f) {
#pragma unroll
        for (int bt = 0; bt < 8; ++bt) {
            int mlo = wm + f * 16 + gr;
            int n = wn + bt * 8 + 2 * q;
            if (MODE == 0) {
                size_t zi = (size_t)(m0 + mlo) * HH + n0 + n;
                *(float2*)(g_Z + zi) =
                    make_float2(acc[f][bt][0] + bs0[bt], acc[f][bt][1] + bs1[bt]);
                *(float2*)(g_Z + zi + (size_t)8 * HH) =
                    make_float2(acc[f][bt][2] + bs0[bt], acc[f][bt][3] + bs1[bt]);
            } else {
                size_t oi = (size_t)(m0 + mlo) * OO + n0 + n;
                *(float2*)(outp + oi) =
                    make_float2(sigf(acc[f][bt][0] + bs0[bt]), sigf(acc[f][bt][1] + bs1[bt]));
                *(float2*)(outp + oi + (size_t)8 * OO) =
                    make_float2(sigf(acc[f][bt][2] + bs0[bt]), sigf(acc[f][bt][3] + bs1[bt]));
            }
        }
    }
}

// ---------------- persistent recurrence: aa ONLY, 128 CTAs --------------------
// Warp w owns k-eighth [256w,+256) of a_it -> produced ENTIRELY by slice group w
// (slices 8w..8w+7, same mh). Per-warp dataflow: warp w polls ONLY flag[w] once
// per step, then runs its private cp.async ring with NO block syncs in the
// mainloop. CTA syncs only at reduction and publish.
#define NCTA_R 128
#define WPAD 2056
#define NCH 8
#define AWSTR 40                                     // 32 + 8 pad (16B-aligned rows)
#define AWBUF (32 * AWSTR)                           // 1280 halves per buffer
#define AWRING (3 * AWBUF)                           // 3840 halves = 7680 B per warp
#define ZSTR 36
#define OFF_W 0
#define OFF_A (32 * WPAD * 2)                        // 131584
#define OFF_RED (OFF_A + 8 * AWRING * 2)             // 131584 + 61440 = 193024
#define OFF_Z (OFF_RED + 8 * 32 * 32 * 4)            // + 32768 = 225792
#define PERS_SMEM (OFF_Z + 32 * ZSTR * 4)            // + 4608 = 230400

__global__ void __launch_bounds__(256) rnn_persistent() {
    extern __shared__ __align__(16) unsigned char smraw[];
    __half* Wsm = (__half*)(smraw + OFF_W);        // [32][WPAD]
    __half* Asm = (__half*)(smraw + OFF_A);        // [8 w][3][32][AWSTR]
    float*  red = (float*)(smraw + OFF_RED);       // [8 w][32][32]
    float*  Zsm = (float*)(smraw + OFF_Z);         // [32][ZSTR]

    const int tid = threadIdx.x;
    const int lane = tid & 31, warp = tid >> 5;
    const int cta = blockIdx.x;
    const int slice = cta & 63;
    const int mh = cta >> 6;                 // 0..1
    const int n0 = slice * 32;
    const int row0 = mh * 32;
    const unsigned* myWflag = &g_barh[((size_t)mh * 8 + warp) * 32];   // warp's producer
    unsigned* myflag = &g_barh[((size_t)mh * 8 + (slice >> 3)) * 32];  // this CTA's group

    // Z slice loader: 32 rows x 32 floats = 256 16B segs, 1/thread
    auto loadZ = [&](int it) {
        int row = tid >> 3, j = tid & 7;
        cp_async16(Zsm + row * ZSTR + j * 4,
                   g_Z + ((size_t)it * 64 + row0 + row) * HH + n0 + j * 4);
    };

    // persistent W_aa slice: 32 rows x 2048 halves
    for (int u = tid; u < 32 * 256; u += 256) {
        int row = u >> 8, cg = u & 255;
        cp_async16(Wsm + row * WPAD + cg * 8, g_Waa + (size_t)(n0 + row) * HH + cg * 8);
    }
    cp_commit();
    cp_wait0();
    __syncthreads();

    const int gr = lane >> 2, q = lane & 3;
    const int arow = ((lane >> 3) & 1) * 8 + (lane & 7);
    const int akoff = (lane >> 4) * 8;
    const int brow = (lane >> 4) * 8 + (lane & 7);
    const int bkoff = ((lane >> 3) & 1) * 8;

    __half* Aw = Asm + (size_t)warp * AWRING;    // this warp's private ring

    // per-warp chunk loader: 32 rows x 32 cols = 128 16B segs, 4/lane
    auto loadA = [&](int buf, int c, const __half* a_src) {
#pragma unroll
        for (int r = 0; r < 4; ++r) {
            int idx = lane + r * 32;
            int row = idx >> 2, j = idx & 3;
            cp_async16(Aw + buf * AWBUF + row * AWSTR + j * 8,
                       a_src + (size_t)(row0 + row) * HH + warp * 256 + c * 32 + j * 8);
        }
    };

    // epilogue indices: thread handles 4 consecutive cols of one row
    const int erow = tid >> 3;            // 0..31
    const int ecol = (tid & 7) * 4;       // 0,4,..,28

    for (int it = 0; it < TT; ++it) {
        const __half* a_cur = g_ahist + (size_t)it * NA0;
        const unsigned tgt = (unsigned)it * 8u;

        float acc[2][4][4];
#pragma unroll
        for (int f = 0; f < 2; ++f)
#pragma unroll
            for (int bs = 0; bs < 4; ++bs)
#pragma unroll
                for (int c = 0; c < 4; ++c) acc[f][bs][c] = 0.0f;

        // warp-local producer wait (8 polls run in parallel across warps)
        if (lane == 0) {
            while (ld_acq(myWflag) < tgt) { }
        }
        __syncwarp();

        // prologue: Z (consumed only at epilogue) + chunks 0,1
        loadZ(it);
        loadA(0, 0, a_cur); cp_commit();
        loadA(1, 1, a_cur); cp_commit();

        for (int c = 0; c < NCH; ++c) {
            if (c < NCH - 1) cp_wait1(); else cp_wait0();
            // per-warp ring: buffer (c+2)%3 was consumed by THIS warp at c-1
            if (c + 2 < NCH) { loadA((c + 2) % 3, c + 2, a_cur); cp_commit(); }

            const __half* Ab = Aw + (c % 3) * AWBUF;
#pragma unroll
            for (int s = 0; s < 2; ++s) {
                uint32_t a[2][4];
#pragma unroll
                for (int f = 0; f < 2; ++f)
                    ldsm4(a[f][0], a[f][1], a[f][2], a[f][3],
                          Ab + (f * 16 + arow) * AWSTR + s * 16 + akoff);
                int bcol = warp * 256 + c * 32 + s * 16 + bkoff;
                uint32_t bl0, bl1, bl2, bl3, bu0, bu1, bu2, bu3;
                ldsm4(bl0, bl1, bl2, bl3, Wsm + brow * WPAD + bcol);
                ldsm4(bu0, bu1, bu2, bu3, Wsm + (brow + 16) * WPAD + bcol);
#pragma unroll
                for (int f = 0; f < 2; ++f) {
                    mma16816(acc[f][0], a[f], bl0, bl1);
                    mma16816(acc[f][1], a[f], bl2, bl3);
                    mma16816(acc[f][2], a[f], bu0, bu1);
                    mma16816(acc[f][3], a[f], bu2, bu3);
                }
            }
        }

        // ---- write partials (own region, no sync needed before) ----
        {
            float* rp = red + (size_t)warp * 1024;
#pragma unroll
            for (int f = 0; f < 2; ++f)
#pragma unroll
                for (int bs = 0; bs < 4; ++bs) {
                    int row = f * 16 + gr, col = bs * 8 + 2 * q;
                    *(float2*)(rp + row * 32 + col) = make_float2(acc[f][bs][0], acc[f][bs][1]);
                    *(float2*)(rp + (row + 8) * 32 + col) = make_float2(acc[f][bs][2], acc[f][bs][3]);
                }
        }
        __syncthreads();   // all warps' partials + Z visible

        // ---- distributed reduce + sigmoid + store (4 outputs/thread) ----
        {
            float4 sum = *(const float4*)(red + (size_t)erow * 32 + ecol);
#pragma unroll
            for (int p = 1; p < 8; ++p) {
                float4 v = *(const float4*)(red + (size_t)p * 1024 + erow * 32 + ecol);
                sum.x += v.x; sum.y += v.y; sum.z += v.z; sum.w += v.w;
            }
            float4 z = *(const float4*)(Zsm + erow * ZSTR + ecol);
            __half2 h0 = __floats2half2_rn(sigf(sum.x + z.x), sigf(sum.y + z.y));
            __half2 h1 = __floats2half2_rn(sigf(sum.z + z.z), sigf(sum.w + z.w));
            __half* adst = g_ahist + (size_t)(it + 1) * NA0
                         + (size_t)(row0 + erow) * HH + n0 + ecol;
            *(uint2*)adst = make_uint2(*(uint32_t*)&h0, *(uint32_t*)&h1);
        }

        // publish a_{it+1} for this slice's group
        __syncthreads();                 // all stores of this CTA complete
        if (tid == 0) red_rel_add1(myflag);
    }
}

// ---------------- launch ----------------
extern "C" void kernel_launch(void* const* d_in, const int* in_sizes, int n_in,
                              void* d_out, int out_size) {
    const float* x    = (const float*)d_in[0];
    const float* Waa  = (const float*)d_in[1];
    const float* b_aa = (const float*)d_in[2];
    const float* Wax  = (const float*)d_in[3];
    const float* b_ax = (const float*)d_in[4];
    const float* Wya  = (const float*)d_in[5];
    const float* b_ya = (const float*)d_in[6];
    float* out = (float*)d_out;

    static bool attr_done = false;
    if (!attr_done) {
        cudaFuncSetAttribute(big_gemm<0>, cudaFuncAttributeMaxDynamicSharedMemorySize, XP_SMEM);
        cudaFuncSetAttribute(big_gemm<1>, cudaFuncAttributeMaxDynamicSharedMemorySize, XP_SMEM);
        cudaFuncSetAttribute(rnn_persistent, cudaFuncAttributeMaxDynamicSharedMemorySize, PERS_SMEM);
        attr_done = true;
    }

    int prep_blocks = (int)((NPREP4 + 255) / 256);
    prep_kernel<<<prep_blocks, 256>>>(x, Waa, Wax, Wya);

    dim3 xg(HH / 128, (TT * BB) / 128);   // 16 x 128
    big_gemm<0><<<xg, 256, XP_SMEM>>>(b_ax, b_aa, nullptr);

    rnn_persistent<<<NCTA_R, 256, PERS_SMEM>>>();

    dim3 yg(OO / 128, (TT * BB) / 128);   // 8 x 128
    big_gemm<1><<<yg, 256, XP_SMEM>>>(b_ya, nullptr, out);
}